// round 2
// baseline (speedup 1.0000x reference)
#include <cuda_runtime.h>
#include <cuda_bf16.h>
#include <cstdint>

// ============================================================================
// Fused 2-layer SimpleRNN: emb[tokens] -> RNN1 -> RNN2 -> dense -> sigmoid
// B=16384, T=80, E=100, U=64.
// mma.sync.m16n8k16 bf16 (compute_103-safe; tcgen05 rejected by this
// toolchain's compute_103 ptxas stage).
// 128 CTAs x 256 thr; each warp owns 16 batch rows, fully independent:
// no __syncthreads in the T-loop, hidden state in warp-private SMEM rows.
// ============================================================================

#define B_TOT   16384
#define T_SEQ   80
#define E_DIM   100
#define U_DIM   64
#define M_TILE  128
#define NTHR    256

// SMEM strides (bf16 elems / bytes). Odd multiple of 16B -> conflict-free ldmatrix.
#define XSTR    120     // x tile row: 120 bf16 = 240 B (cols 0..99 data, 100..119 zero)
#define XSTRB   240
#define HSTR    72      // h / wh tiles: 72 bf16 = 144 B (cols 0..63 data)
#define HSTRB   144

// SMEM layout (bytes)
#define OFF_X    0                        // 128 * 240 = 30720
#define OFF_W1   (OFF_X  + M_TILE*XSTRB)  // 64 * 240  = 15360  (Wx1^T, k-padded)
#define OFF_WH1  (OFF_W1 + U_DIM*XSTRB)   // 64 * 144
#define OFF_WX2  (OFF_WH1 + U_DIM*HSTRB)
#define OFF_WH2  (OFF_WX2 + U_DIM*HSTRB)
#define OFF_H1   (OFF_WH2 + U_DIM*HSTRB)  // 128 * 144
#define OFF_H2   (OFF_H1 + M_TILE*HSTRB)
#define OFF_B1   (OFF_H2 + M_TILE*HSTRB)  // 64 floats
#define OFF_B2   (OFF_B1 + 256)
#define OFF_WD   (OFF_B2 + 256)
#define OFF_BD   (OFF_WD + 256)
#define SMEM_TOTAL (OFF_BD + 16)

// ---------------------------------------------------------------------------
__device__ __forceinline__ uint32_t smem_u32(const void* p) {
    uint32_t a;
    asm("{ .reg .u64 t; cvta.to.shared.u64 t, %1; cvt.u32.u64 %0, t; }"
        : "=r"(a) : "l"(p));
    return a;
}

__device__ __forceinline__ float tanh_fast(float x) {
    float y;
    asm("tanh.approx.f32 %0, %1;" : "=f"(y) : "f"(x));
    return y;
}

// pack two fp32 -> bf16x2 (lo = first arg)
__device__ __forceinline__ uint32_t pack_bf16x2(float lo, float hi) {
    uint32_t r;
    asm("cvt.rn.bf16x2.f32 %0, %1, %2;" : "=r"(r) : "f"(hi), "f"(lo));
    return r;
}

__device__ __forceinline__ void ldsm4(uint32_t a[4], uint32_t addr) {
    asm volatile("ldmatrix.sync.aligned.m8n8.x4.shared.b16 {%0,%1,%2,%3}, [%4];"
                 : "=r"(a[0]), "=r"(a[1]), "=r"(a[2]), "=r"(a[3]) : "r"(addr));
}

__device__ __forceinline__ void mma16816(float c[4], const uint32_t a[4],
                                         uint32_t b0, uint32_t b1) {
    asm volatile("mma.sync.aligned.m16n8k16.row.col.f32.bf16.bf16.f32 "
                 "{%0,%1,%2,%3}, {%4,%5,%6,%7}, {%8,%9}, {%0,%1,%2,%3};"
                 : "+f"(c[0]), "+f"(c[1]), "+f"(c[2]), "+f"(c[3])
                 : "r"(a[0]), "r"(a[1]), "r"(a[2]), "r"(a[3]),
                   "r"(b0), "r"(b1));
}

// ---------------------------------------------------------------------------
__global__ void __launch_bounds__(NTHR, 1)
rnn_fused_kernel(const int* __restrict__ tokens,
                 const float* __restrict__ emb,
                 const float* __restrict__ Wx1, const float* __restrict__ Wh1,
                 const float* __restrict__ b1,
                 const float* __restrict__ Wx2, const float* __restrict__ Wh2,
                 const float* __restrict__ b2,
                 const float* __restrict__ Wd, const float* __restrict__ bd,
                 float* __restrict__ out)
{
    extern __shared__ unsigned char sm[];
    const uint32_t smb = smem_u32(sm);

    const int tid  = threadIdx.x;
    const int wid  = tid >> 5;
    const int lane = tid & 31;
    const int m0   = wid * 16;                       // warp's row base in CTA tile
    const int growbase = blockIdx.x * M_TILE + m0;   // global row base for warp

    // ------------------ one-time init (weights, biases, zero state) ---------
    // zero x tile (pad cols stay zero forever; gather rewrites cols 0..99)
    {
        uint32_t* xz = (uint32_t*)(sm + OFF_X);
        for (int i = tid; i < M_TILE * XSTR / 2; i += NTHR) xz[i] = 0u;
        uint32_t* hz1 = (uint32_t*)(sm + OFF_H1);
        uint32_t* hz2 = (uint32_t*)(sm + OFF_H2);
        for (int i = tid; i < M_TILE * HSTR / 2; i += NTHR) { hz1[i] = 0u; hz2[i] = 0u; }
    }
    // Wx1^T: [n][k] with k padded to 120 (k>=100 -> 0)
    {
        __nv_bfloat16* w = (__nv_bfloat16*)(sm + OFF_W1);
        for (int i = tid; i < U_DIM * XSTR; i += NTHR) {
            int n = i / XSTR, k = i % XSTR;
            w[i] = (k < E_DIM) ? __float2bfloat16(Wx1[k * U_DIM + n]) : __float2bfloat16(0.0f);
        }
    }
    // Wh1^T, Wx2^T, Wh2^T: [n][k] stride 72 (k>=64 -> 0)
    {
        __nv_bfloat16* wh1 = (__nv_bfloat16*)(sm + OFF_WH1);
        __nv_bfloat16* wx2 = (__nv_bfloat16*)(sm + OFF_WX2);
        __nv_bfloat16* wh2 = (__nv_bfloat16*)(sm + OFF_WH2);
        for (int i = tid; i < U_DIM * HSTR; i += NTHR) {
            int n = i / HSTR, k = i % HSTR;
            bool ok = (k < U_DIM);
            wh1[i] = ok ? __float2bfloat16(Wh1[k * U_DIM + n]) : __float2bfloat16(0.0f);
            wx2[i] = ok ? __float2bfloat16(Wx2[k * U_DIM + n]) : __float2bfloat16(0.0f);
            wh2[i] = ok ? __float2bfloat16(Wh2[k * U_DIM + n]) : __float2bfloat16(0.0f);
        }
    }
    {
        float* b1s = (float*)(sm + OFF_B1);
        float* b2s = (float*)(sm + OFF_B2);
        float* wds = (float*)(sm + OFF_WD);
        if (tid < U_DIM) { b1s[tid] = b1[tid]; b2s[tid] = b2[tid]; wds[tid] = Wd[tid]; }
        if (tid == 0) *(float*)(sm + OFF_BD) = bd[0];
    }
    __syncthreads();

    // ------------------ per-warp pointers / addresses ----------------------
    const uint32_t xbase   = smb + OFF_X;
    const uint32_t w1base  = smb + OFF_W1;
    const uint32_t wh1base = smb + OFF_WH1;
    const uint32_t wx2base = smb + OFF_WX2;
    const uint32_t wh2base = smb + OFF_WH2;
    const uint32_t h1base  = smb + OFF_H1;
    const uint32_t h2base  = smb + OFF_H2;
    const float* b1s = (const float*)(sm + OFF_B1);
    const float* b2s = (const float*)(sm + OFF_B2);

    // A-operand ldmatrix lane address offsets
    const uint32_t aRow = (uint32_t)(lane & 15);
    const uint32_t aK16 = (uint32_t)(lane >> 4) * 16;   // +16B for k-hi half
    // B-operand ldmatrix lane address pieces: covers 2 n-tiles per x4
    const uint32_t bRow = (uint32_t)((lane & 7) + ((lane >> 4) << 3));
    const uint32_t bK16 = (uint32_t)((lane >> 3) & 1) * 16;

    const uint32_t xA_lane  = xbase  + (m0 + aRow) * XSTRB + aK16;  // + kt*32
    const uint32_t h1A_lane = h1base + (m0 + aRow) * HSTRB + aK16;
    const uint32_t h2A_lane = h2base + (m0 + aRow) * HSTRB + aK16;
    const uint32_t w1B_lane  = w1base  + bRow * XSTRB + bK16;       // + np*16*XSTRB + kt*32
    const uint32_t wh1B_lane = wh1base + bRow * HSTRB + bK16;
    const uint32_t wx2B_lane = wx2base + bRow * HSTRB + bK16;
    const uint32_t wh2B_lane = wh2base + bRow * HSTRB + bK16;

    // epilogue store mapping (c-fragment)
    const int cr = lane >> 2;            // row within m16 (plus +8 variant)
    const int cq = (lane & 3) * 2;       // col pair base within n8

    // ------------------ embedding prefetch machinery -----------------------
    // warp gathers its 16 rows x 25 float4 chunks = 400 chunks, 13 per lane
    const float4* emb4 = (const float4*)emb;
    float4 pv[13];
    int    tokreg;

    auto prefetch = [&](int t) {
        tokreg = 0;
        if (lane < 16) tokreg = tokens[(growbase + lane) * T_SEQ + t];
#pragma unroll
        for (int i = 0; i < 13; i++) {
            int c = lane + 32 * i;
            int r = (c < 400) ? (c / 25) : 0;
            int trow = __shfl_sync(0xffffffffu, tokreg, r);
            if (c < 400) {
                int ch = c - r * 25;
                pv[i] = __ldg(&emb4[(size_t)trow * 25 + ch]);
            }
        }
    };

    auto store_x = [&]() {
#pragma unroll
        for (int i = 0; i < 13; i++) {
            int c = lane + 32 * i;
            if (c < 400) {
                int r = c / 25;
                int ch = c - r * 25;
                uint32_t p0 = pack_bf16x2(pv[i].x, pv[i].y);
                uint32_t p1 = pack_bf16x2(pv[i].z, pv[i].w);
                uint2* dst = (uint2*)(sm + OFF_X + (m0 + r) * XSTRB + ch * 8);
                *dst = make_uint2(p0, p1);
            }
        }
    };

    prefetch(0);

    // ------------------ T loop (warp-private, no __syncthreads) ------------
    for (int t = 0; t < T_SEQ; ++t) {
        store_x();
        __syncwarp();
        if (t < T_SEQ - 1) prefetch(t + 1);     // LDGs overlap MMAs below

        // ---- layer 1: acc = x @ Wx1 + h1 @ Wh1 ----
        float acc[8][4];
#pragma unroll
        for (int n = 0; n < 8; n++)
#pragma unroll
            for (int j = 0; j < 4; j++) acc[n][j] = 0.0f;

#pragma unroll
        for (int kt = 0; kt < 7; kt++) {
            uint32_t a[4]; ldsm4(a, xA_lane + kt * 32);
#pragma unroll
            for (int np = 0; np < 4; np++) {
                uint32_t b[4]; ldsm4(b, w1B_lane + np * 16 * XSTRB + kt * 32);
                mma16816(acc[2 * np],     a, b[0], b[1]);
                mma16816(acc[2 * np + 1], a, b[2], b[3]);
            }
        }
#pragma unroll
        for (int kt = 0; kt < 4; kt++) {
            uint32_t a[4]; ldsm4(a, h1A_lane + kt * 32);
#pragma unroll
            for (int np = 0; np < 4; np++) {
                uint32_t b[4]; ldsm4(b, wh1B_lane + np * 16 * HSTRB + kt * 32);
                mma16816(acc[2 * np],     a, b[0], b[1]);
                mma16816(acc[2 * np + 1], a, b[2], b[3]);
            }
        }

        // ---- epilogue 1: h1 = tanh(acc + b1) -> SMEM bf16 ----
#pragma unroll
        for (int nt = 0; nt < 8; nt++) {
            int col = nt * 8 + cq;
            float bb0 = b1s[col], bb1 = b1s[col + 1];
            float v0 = tanh_fast(acc[nt][0] + bb0);
            float v1 = tanh_fast(acc[nt][1] + bb1);
            float v2 = tanh_fast(acc[nt][2] + bb0);
            float v3 = tanh_fast(acc[nt][3] + bb1);
            *(uint32_t*)(sm + OFF_H1 + (m0 + cr)     * HSTRB + col * 2) = pack_bf16x2(v0, v1);
            *(uint32_t*)(sm + OFF_H1 + (m0 + cr + 8) * HSTRB + col * 2) = pack_bf16x2(v2, v3);
        }
        __syncwarp();

        // ---- layer 2: acc = h1 @ Wx2 + h2 @ Wh2 ----
#pragma unroll
        for (int n = 0; n < 8; n++)
#pragma unroll
            for (int j = 0; j < 4; j++) acc[n][j] = 0.0f;

#pragma unroll
        for (int kt = 0; kt < 4; kt++) {
            uint32_t a[4]; ldsm4(a, h1A_lane + kt * 32);
#pragma unroll
            for (int np = 0; np < 4; np++) {
                uint32_t b[4]; ldsm4(b, wx2B_lane + np * 16 * HSTRB + kt * 32);
                mma16816(acc[2 * np],     a, b[0], b[1]);
                mma16816(acc[2 * np + 1], a, b[2], b[3]);
            }
        }
#pragma unroll
        for (int kt = 0; kt < 4; kt++) {
            uint32_t a[4]; ldsm4(a, h2A_lane + kt * 32);
#pragma unroll
            for (int np = 0; np < 4; np++) {
                uint32_t b[4]; ldsm4(b, wh2B_lane + np * 16 * HSTRB + kt * 32);
                mma16816(acc[2 * np],     a, b[0], b[1]);
                mma16816(acc[2 * np + 1], a, b[2], b[3]);
            }
        }

        // ---- epilogue 2: h2 = tanh(acc + b2) -> SMEM bf16 ----
#pragma unroll
        for (int nt = 0; nt < 8; nt++) {
            int col = nt * 8 + cq;
            float bb0 = b2s[col], bb1 = b2s[col + 1];
            float v0 = tanh_fast(acc[nt][0] + bb0);
            float v1 = tanh_fast(acc[nt][1] + bb1);
            float v2 = tanh_fast(acc[nt][2] + bb0);
            float v3 = tanh_fast(acc[nt][3] + bb1);
            *(uint32_t*)(sm + OFF_H2 + (m0 + cr)     * HSTRB + col * 2) = pack_bf16x2(v0, v1);
            *(uint32_t*)(sm + OFF_H2 + (m0 + cr + 8) * HSTRB + col * 2) = pack_bf16x2(v2, v3);
        }
        __syncwarp();
    }

    // ------------------ final dense + sigmoid (warp-private rows) ----------
    if (lane < 16) {
        const float* wds = (const float*)(sm + OFF_WD);
        const __nv_bfloat162* hrow =
            (const __nv_bfloat162*)(sm + OFF_H2 + (m0 + lane) * HSTRB);
        float logit = *(const float*)(sm + OFF_BD);
#pragma unroll
        for (int j = 0; j < 32; j++) {
            float2 hv = __bfloat1622float2(hrow[j]);
            logit = fmaf(hv.x, wds[2 * j], logit);
            logit = fmaf(hv.y, wds[2 * j + 1], logit);
        }
        out[growbase + lane] = 1.0f / (1.0f + __expf(-logit));
    }
}

// ---------------------------------------------------------------------------
extern "C" void kernel_launch(void* const* d_in, const int* in_sizes, int n_in,
                              void* d_out, int out_size) {
    (void)in_sizes; (void)n_in; (void)out_size;
    // Not a stream op -> graph-capture safe; idempotent.
    cudaFuncSetAttribute(rnn_fused_kernel,
                         cudaFuncAttributeMaxDynamicSharedMemorySize, SMEM_TOTAL);
    rnn_fused_kernel<<<B_TOT / M_TILE, NTHR, SMEM_TOTAL>>>(
        (const int*)d_in[0],   // tokens
        (const float*)d_in[1], // emb
        (const float*)d_in[2], // Wx1
        (const float*)d_in[3], // Wh1
        (const float*)d_in[4], // b1
        (const float*)d_in[5], // Wx2
        (const float*)d_in[6], // Wh2
        (const float*)d_in[7], // b2
        (const float*)d_in[8], // Wd
        (const float*)d_in[9], // bd
        (float*)d_out);
}

// round 3
// speedup vs baseline: 1.6589x; 1.6589x over previous
#include <cuda_runtime.h>
#include <cuda_bf16.h>
#include <cstdint>

// ============================================================================
// Fused 2-layer SimpleRNN, round 3.
// Key change vs R2: emb@Wx1+b1 folded into a precomputed 10000x64 table E'
// (kernel 1), so the T-loop (kernel 2) does only h1@Wh1 and h1@Wx2+h2@Wh2.
// Layer-2 weights live in registers; per-step LDSM drops 95 -> 28.
// ============================================================================

#define VOCAB   10000
#define B_TOT   16384
#define T_SEQ   80
#define E_DIM   100
#define U_DIM   64
#define M_TILE  128
#define NTHR    256

#define HSTR    72      // h/w tile row stride: 72 bf16 = 144 B (conflict-free ldsm)
#define HSTRB   144

// SMEM layout (bytes)
#define OFF_H1   0                          // 128*144
#define OFF_H2   (OFF_H1 + M_TILE*HSTRB)
#define OFF_WH1  (OFF_H2 + M_TILE*HSTRB)    // 64*144
#define OFF_WX2  (OFF_WH1 + U_DIM*HSTRB)
#define OFF_WH2  (OFF_WX2 + U_DIM*HSTRB)
#define OFF_WD   (OFF_WH2 + U_DIM*HSTRB)    // 64 floats
#define SMEM_TOTAL (OFF_WD + 256 + 16)

// Projected embedding table: E'[v][u] = sum_k emb[v][k]*Wx1[k][u] + b1[u]
__device__ __nv_bfloat16 g_Etab[VOCAB * U_DIM];

// ---------------------------------------------------------------------------
__device__ __forceinline__ uint32_t smem_u32(const void* p) {
    uint32_t a;
    asm("{ .reg .u64 t; cvta.to.shared.u64 t, %1; cvt.u32.u64 %0, t; }"
        : "=r"(a) : "l"(p));
    return a;
}
__device__ __forceinline__ float tanh_fast(float x) {
    float y; asm("tanh.approx.f32 %0, %1;" : "=f"(y) : "f"(x)); return y;
}
__device__ __forceinline__ uint32_t pack_bf16x2(float lo, float hi) {
    uint32_t r;
    asm("cvt.rn.bf16x2.f32 %0, %1, %2;" : "=r"(r) : "f"(hi), "f"(lo));
    return r;
}
__device__ __forceinline__ void ldsm4(uint32_t a[4], uint32_t addr) {
    asm volatile("ldmatrix.sync.aligned.m8n8.x4.shared.b16 {%0,%1,%2,%3}, [%4];"
                 : "=r"(a[0]), "=r"(a[1]), "=r"(a[2]), "=r"(a[3]) : "r"(addr));
}
__device__ __forceinline__ void mma16816(float c[4], const uint32_t a[4],
                                         uint32_t b0, uint32_t b1) {
    asm volatile("mma.sync.aligned.m16n8k16.row.col.f32.bf16.bf16.f32 "
                 "{%0,%1,%2,%3}, {%4,%5,%6,%7}, {%8,%9}, {%0,%1,%2,%3};"
                 : "+f"(c[0]), "+f"(c[1]), "+f"(c[2]), "+f"(c[3])
                 : "r"(a[0]), "r"(a[1]), "r"(a[2]), "r"(a[3]),
                   "r"(b0), "r"(b1));
}

// ---------------------------------------------------------------------------
// Kernel 1: E'[v][u] = emb[v]@Wx1[:,u] + b1[u]  (bf16 out)
// ---------------------------------------------------------------------------
__global__ void xproj_kernel(const float* __restrict__ emb,
                             const float* __restrict__ Wx1,
                             const float* __restrict__ b1)
{
    int u = threadIdx.x;                       // 0..63
    int v = blockIdx.x * 4 + threadIdx.y;      // vocab row
    if (v >= VOCAB) return;
    float s = b1[u];
    const float* er = emb + (size_t)v * E_DIM;
#pragma unroll 5
    for (int k = 0; k < E_DIM; k++)
        s = fmaf(__ldg(er + k), __ldg(Wx1 + k * U_DIM + u), s);
    g_Etab[v * U_DIM + u] = __float2bfloat16(s);
}

// ---------------------------------------------------------------------------
// Kernel 2: recurrent loop. Each warp owns 16 batch rows, fully independent.
// ---------------------------------------------------------------------------
__global__ void __launch_bounds__(NTHR, 1)
rnn_loop_kernel(const int* __restrict__ tokens,
                const float* __restrict__ Wh1,
                const float* __restrict__ Wx2, const float* __restrict__ Wh2,
                const float* __restrict__ b2,
                const float* __restrict__ Wd, const float* __restrict__ bd,
                float* __restrict__ out)
{
    extern __shared__ unsigned char sm[];
    const uint32_t smb = smem_u32(sm);

    const int tid  = threadIdx.x;
    const int wid  = tid >> 5;
    const int lane = tid & 31;
    const int m0   = wid * 16;
    const int growbase = blockIdx.x * M_TILE + m0;

    // ---- init: zero state, build W^T tiles [n][k] stride 72 -------------
    {
        uint32_t* hz1 = (uint32_t*)(sm + OFF_H1);
        uint32_t* hz2 = (uint32_t*)(sm + OFF_H2);
        for (int i = tid; i < M_TILE * HSTR / 2; i += NTHR) { hz1[i] = 0u; hz2[i] = 0u; }
        __nv_bfloat16* wh1 = (__nv_bfloat16*)(sm + OFF_WH1);
        __nv_bfloat16* wx2 = (__nv_bfloat16*)(sm + OFF_WX2);
        __nv_bfloat16* wh2 = (__nv_bfloat16*)(sm + OFF_WH2);
        for (int i = tid; i < U_DIM * HSTR; i += NTHR) {
            int n = i / HSTR, k = i % HSTR;
            bool ok = (k < U_DIM);
            wh1[i] = ok ? __float2bfloat16(Wh1[k * U_DIM + n]) : __float2bfloat16(0.0f);
            wx2[i] = ok ? __float2bfloat16(Wx2[k * U_DIM + n]) : __float2bfloat16(0.0f);
            wh2[i] = ok ? __float2bfloat16(Wh2[k * U_DIM + n]) : __float2bfloat16(0.0f);
        }
        if (tid < U_DIM) ((float*)(sm + OFF_WD))[tid] = Wd[tid];
    }
    __syncthreads();

    // ---- ldmatrix lane addressing ---------------------------------------
    const uint32_t aRow = (uint32_t)(lane & 15);
    const uint32_t aK16 = (uint32_t)(lane >> 4) * 16;
    const uint32_t bRow = (uint32_t)((lane & 7) + ((lane >> 4) << 3));
    const uint32_t bK16 = (uint32_t)((lane >> 3) & 1) * 16;

    const uint32_t h1A_lane  = smb + OFF_H1  + (m0 + aRow) * HSTRB + aK16;
    const uint32_t h2A_lane  = smb + OFF_H2  + (m0 + aRow) * HSTRB + aK16;
    const uint32_t wh1B_lane = smb + OFF_WH1 + bRow * HSTRB + bK16;
    const uint32_t wx2B_lane = smb + OFF_WX2 + bRow * HSTRB + bK16;
    const uint32_t wh2B_lane = smb + OFF_WH2 + bRow * HSTRB + bK16;

    const int cr = lane >> 2;            // c-frag row within m16
    const int cq = (lane & 3) * 2;       // c-frag col pair base within n8

    // ---- hoist layer-2 weights into registers (128 regs) -----------------
    uint32_t wx2r[4][4][4], wh2r[4][4][4];
#pragma unroll
    for (int kt = 0; kt < 4; kt++)
#pragma unroll
        for (int np = 0; np < 4; np++) {
            ldsm4(wx2r[kt][np], wx2B_lane + np * 16 * HSTRB + kt * 32);
            ldsm4(wh2r[kt][np], wh2B_lane + np * 16 * HSTRB + kt * 32);
        }

    // ---- per-lane b2 pairs (layer-2 acc init) ----------------------------
    float2 b2r[8];
#pragma unroll
    for (int nt = 0; nt < 8; nt++) {
        int col = nt * 8 + cq;
        b2r[nt] = make_float2(__ldg(b2 + col), __ldg(b2 + col + 1));
    }

    // ---- E' gather prefetch ----------------------------------------------
    const uint32_t* Et32 = (const uint32_t*)g_Etab;
    uint32_t evp[16];
    int tokreg = 0;

    auto prefetch = [&](int t) {
        int r = 0;
        if (lane < 16) r = __ldg(tokens + (size_t)(growbase + lane) * T_SEQ + t);
        tokreg = r;
        int tokA = __shfl_sync(0xffffffffu, tokreg, cr);
        int tokB = __shfl_sync(0xffffffffu, tokreg, cr + 8);
        const uint32_t* EA = Et32 + tokA * 32 + (cq >> 1);
        const uint32_t* EB = Et32 + tokB * 32 + (cq >> 1);
#pragma unroll
        for (int nt = 0; nt < 8; nt++) {
            evp[2 * nt]     = __ldg(EA + nt * 4);
            evp[2 * nt + 1] = __ldg(EB + nt * 4);
        }
    };

    prefetch(0);

    // ---- T loop (warp-private; no __syncthreads) -------------------------
    for (int t = 0; t < T_SEQ; ++t) {
        // acc init = xp (= x@Wx1 + b1) from prefetched E' (exact bf16->f32)
        float acc[8][4];
#pragma unroll
        for (int nt = 0; nt < 8; nt++) {
            uint32_t e0 = evp[2 * nt], e1 = evp[2 * nt + 1];
            acc[nt][0] = __uint_as_float(e0 << 16);
            acc[nt][1] = __uint_as_float(e0 & 0xffff0000u);
            acc[nt][2] = __uint_as_float(e1 << 16);
            acc[nt][3] = __uint_as_float(e1 & 0xffff0000u);
        }
        if (t + 1 < T_SEQ) prefetch(t + 1);     // LDGs overlap MMAs below

        // ---- layer 1: acc += h1 @ Wh1 ----
#pragma unroll
        for (int kt = 0; kt < 4; kt++) {
            uint32_t a[4]; ldsm4(a, h1A_lane + kt * 32);
#pragma unroll
            for (int np = 0; np < 4; np++) {
                uint32_t b[4]; ldsm4(b, wh1B_lane + np * 16 * HSTRB + kt * 32);
                mma16816(acc[2 * np],     a, b[0], b[1]);
                mma16816(acc[2 * np + 1], a, b[2], b[3]);
            }
        }

        // ---- epilogue 1: h1 = tanh(acc) -> SMEM bf16 ----
#pragma unroll
        for (int nt = 0; nt < 8; nt++) {
            int col = nt * 8 + cq;
            float v0 = tanh_fast(acc[nt][0]);
            float v1 = tanh_fast(acc[nt][1]);
            float v2 = tanh_fast(acc[nt][2]);
            float v3 = tanh_fast(acc[nt][3]);
            *(uint32_t*)(sm + OFF_H1 + (m0 + cr)     * HSTRB + col * 2) = pack_bf16x2(v0, v1);
            *(uint32_t*)(sm + OFF_H1 + (m0 + cr + 8) * HSTRB + col * 2) = pack_bf16x2(v2, v3);
        }
        __syncwarp();

        // ---- layer 2: acc = b2 + h1 @ Wx2 + h2 @ Wh2 ----
#pragma unroll
        for (int nt = 0; nt < 8; nt++) {
            acc[nt][0] = b2r[nt].x; acc[nt][1] = b2r[nt].y;
            acc[nt][2] = b2r[nt].x; acc[nt][3] = b2r[nt].y;
        }
#pragma unroll
        for (int kt = 0; kt < 4; kt++) {
            uint32_t a[4]; ldsm4(a, h1A_lane + kt * 32);
#pragma unroll
            for (int np = 0; np < 4; np++) {
                mma16816(acc[2 * np],     a, wx2r[kt][np][0], wx2r[kt][np][1]);
                mma16816(acc[2 * np + 1], a, wx2r[kt][np][2], wx2r[kt][np][3]);
            }
        }
#pragma unroll
        for (int kt = 0; kt < 4; kt++) {
            uint32_t a[4]; ldsm4(a, h2A_lane + kt * 32);
#pragma unroll
            for (int np = 0; np < 4; np++) {
                mma16816(acc[2 * np],     a, wh2r[kt][np][0], wh2r[kt][np][1]);
                mma16816(acc[2 * np + 1], a, wh2r[kt][np][2], wh2r[kt][np][3]);
            }
        }

        // ---- epilogue 2: h2 = tanh(acc) -> SMEM bf16 ----
#pragma unroll
        for (int nt = 0; nt < 8; nt++) {
            int col = nt * 8 + cq;
            float v0 = tanh_fast(acc[nt][0]);
            float v1 = tanh_fast(acc[nt][1]);
            float v2 = tanh_fast(acc[nt][2]);
            float v3 = tanh_fast(acc[nt][3]);
            *(uint32_t*)(sm + OFF_H2 + (m0 + cr)     * HSTRB + col * 2) = pack_bf16x2(v0, v1);
            *(uint32_t*)(sm + OFF_H2 + (m0 + cr + 8) * HSTRB + col * 2) = pack_bf16x2(v2, v3);
        }
        __syncwarp();
    }

    // ---- final dense + sigmoid ------------------------------------------
    if (lane < 16) {
        const float* wds = (const float*)(sm + OFF_WD);
        const __nv_bfloat162* hrow =
            (const __nv_bfloat162*)(sm + OFF_H2 + (m0 + lane) * HSTRB);
        float logit = __ldg(bd);
#pragma unroll
        for (int j = 0; j < 32; j++) {
            float2 hv = __bfloat1622float2(hrow[j]);
            logit = fmaf(hv.x, wds[2 * j], logit);
            logit = fmaf(hv.y, wds[2 * j + 1], logit);
        }
        out[growbase + lane] = 1.0f / (1.0f + __expf(-logit));
    }
}

// ---------------------------------------------------------------------------
extern "C" void kernel_launch(void* const* d_in, const int* in_sizes, int n_in,
                              void* d_out, int out_size) {
    (void)in_sizes; (void)n_in; (void)out_size;
    cudaFuncSetAttribute(rnn_loop_kernel,
                         cudaFuncAttributeMaxDynamicSharedMemorySize, SMEM_TOTAL);

    xproj_kernel<<<(VOCAB + 3) / 4, dim3(64, 4)>>>(
        (const float*)d_in[1],   // emb
        (const float*)d_in[2],   // Wx1
        (const float*)d_in[4]);  // b1

    rnn_loop_kernel<<<B_TOT / M_TILE, NTHR, SMEM_TOTAL>>>(
        (const int*)d_in[0],     // tokens
        (const float*)d_in[3],   // Wh1
        (const float*)d_in[5],   // Wx2
        (const float*)d_in[6],   // Wh2
        (const float*)d_in[7],   // b2
        (const float*)d_in[8],   // Wd
        (const float*)d_in[9],   // bd
        (float*)d_out);
}

// round 6
// speedup vs baseline: 1.8822x; 1.1346x over previous
#include <cuda_runtime.h>
#include <cuda_bf16.h>
#include <cstdint>

// ============================================================================
// Fused 2-layer SimpleRNN, round 5 (= R4 + 2 bugfixes).
// h1/h2 register-resident across timesteps (C-frag == A-frag layout);
// epilogues are pure register ops. E' gather coalesced via LDG.128 into
// warp-private SMEM staging (stores via GENERIC pointer - R4 crash fix),
// then 4 ldsm4. Final dense fragment indices fixed ([0],[2]=row cr).
// ============================================================================

#define VOCAB   10000
#define B_TOT   16384
#define T_SEQ   80
#define E_DIM   100
#define U_DIM   64
#define M_TILE  128
#define NTHR    256

#define HSTRB   144     // W tile row stride bytes (72 bf16)
#define STGSTR  144     // staging row stride bytes
#define STG_PER_WARP (16 * STGSTR)   // 2304 B

// SMEM layout (bytes)
#define OFF_WH1  0                          // 64*144 = 9216 (persistent)
#define OFF_STG  (OFF_WH1 + 64*HSTRB)       // 8 warps * 2304 = 18432
                                            //  (transiently aliased: wx2 tile at
                                            //   OFF_STG, wh2 at OFF_STG+9216)
#define SMEM_TOTAL (OFF_STG + 8*STG_PER_WARP + 64)

// Projected embedding table: E'[v][u] = emb[v]@Wx1[:,u] + b1[u]  (bf16)
__device__ __nv_bfloat16 g_Etab[VOCAB * U_DIM];

// ---------------------------------------------------------------------------
__device__ __forceinline__ uint32_t smem_u32(const void* p) {
    uint32_t a;
    asm("{ .reg .u64 t; cvta.to.shared.u64 t, %1; cvt.u32.u64 %0, t; }"
        : "=r"(a) : "l"(p));
    return a;
}
__device__ __forceinline__ float tanh_fast(float x) {
    float y; asm("tanh.approx.f32 %0, %1;" : "=f"(y) : "f"(x)); return y;
}
__device__ __forceinline__ uint32_t pack_bf16x2(float lo, float hi) {
    uint32_t r;
    asm("cvt.rn.bf16x2.f32 %0, %1, %2;" : "=r"(r) : "f"(hi), "f"(lo));
    return r;
}
__device__ __forceinline__ float bf16_lo(uint32_t p) { return __uint_as_float(p << 16); }
__device__ __forceinline__ float bf16_hi(uint32_t p) { return __uint_as_float(p & 0xffff0000u); }

__device__ __forceinline__ void ldsm4(uint32_t a[4], uint32_t addr) {
    asm volatile("ldmatrix.sync.aligned.m8n8.x4.shared.b16 {%0,%1,%2,%3}, [%4];"
                 : "=r"(a[0]), "=r"(a[1]), "=r"(a[2]), "=r"(a[3]) : "r"(addr));
}
__device__ __forceinline__ void mma16816(float c[4], const uint32_t a[4],
                                         uint32_t b0, uint32_t b1) {
    asm volatile("mma.sync.aligned.m16n8k16.row.col.f32.bf16.bf16.f32 "
                 "{%0,%1,%2,%3}, {%4,%5,%6,%7}, {%8,%9}, {%0,%1,%2,%3};"
                 : "+f"(c[0]), "+f"(c[1]), "+f"(c[2]), "+f"(c[3])
                 : "r"(a[0]), "r"(a[1]), "r"(a[2]), "r"(a[3]),
                   "r"(b0), "r"(b1));
}

// ---------------------------------------------------------------------------
// Kernel 1: E'[v] = emb[v] @ Wx1 + b1
// ---------------------------------------------------------------------------
__global__ void __launch_bounds__(256)
xproj_kernel(const float* __restrict__ emb,
             const float* __restrict__ Wx1,
             const float* __restrict__ b1)
{
    __shared__ float er[4][E_DIM];
    const int tid = threadIdx.y * 64 + threadIdx.x;
    const int v0  = blockIdx.x * 4;

    for (int i = tid; i < 4 * E_DIM; i += 256) {
        int v = i / E_DIM, k = i - v * E_DIM;
        er[v][k] = (v0 + v < VOCAB) ? emb[(size_t)(v0 + v) * E_DIM + k] : 0.0f;
    }
    __syncthreads();

    const int u = threadIdx.x;
    const int v = v0 + threadIdx.y;
    if (v >= VOCAB) return;
    float s = b1[u];
#pragma unroll 4
    for (int k = 0; k < E_DIM; k++)
        s = fmaf(er[threadIdx.y][k], __ldg(Wx1 + k * U_DIM + u), s);
    g_Etab[v * U_DIM + u] = __float2bfloat16(s);
}

// ---------------------------------------------------------------------------
// Kernel 2: recurrent loop. Warp owns 16 rows; h1/h2 live in registers.
// ---------------------------------------------------------------------------
__global__ void __launch_bounds__(NTHR, 1)
rnn_loop_kernel(const int* __restrict__ tokens,
                const float* __restrict__ Wh1,
                const float* __restrict__ Wx2, const float* __restrict__ Wh2,
                const float* __restrict__ b2,
                const float* __restrict__ Wd, const float* __restrict__ bd,
                float* __restrict__ out)
{
    extern __shared__ unsigned char sm[];
    const uint32_t smb = smem_u32(sm);

    const int tid  = threadIdx.x;
    const int wid  = tid >> 5;
    const int lane = tid & 31;
    const int growbase = blockIdx.x * M_TILE + wid * 16;

    // ---- build W^T tiles [n][k], stride 72 bf16 --------------------------
    {
        __nv_bfloat16* wh1 = (__nv_bfloat16*)(sm + OFF_WH1);
        __nv_bfloat16* wx2 = (__nv_bfloat16*)(sm + OFF_STG);          // transient
        __nv_bfloat16* wh2 = (__nv_bfloat16*)(sm + OFF_STG + 9216);   // transient
        for (int i = tid; i < U_DIM * 72; i += NTHR) {
            int n = i / 72, k = i - n * 72;
            bool ok = (k < U_DIM);
            wh1[i] = ok ? __float2bfloat16(Wh1[k * U_DIM + n]) : __float2bfloat16(0.0f);
            wx2[i] = ok ? __float2bfloat16(Wx2[k * U_DIM + n]) : __float2bfloat16(0.0f);
            wh2[i] = ok ? __float2bfloat16(Wh2[k * U_DIM + n]) : __float2bfloat16(0.0f);
        }
    }
    __syncthreads();

    // ---- ldmatrix lane addressing ----------------------------------------
    const uint32_t aRow = (uint32_t)(lane & 15);
    const uint32_t aK16 = (uint32_t)(lane >> 4) * 16;
    const uint32_t bRow = (uint32_t)((lane & 7) + ((lane >> 4) << 3));
    const uint32_t bK16 = (uint32_t)((lane >> 3) & 1) * 16;

    const uint32_t wh1B_lane = smb + OFF_WH1 + bRow * HSTRB + bK16;
    const uint32_t wx2B_lane = smb + OFF_STG + bRow * HSTRB + bK16;
    const uint32_t wh2B_lane = smb + OFF_STG + 9216 + bRow * HSTRB + bK16;

    const int cr = lane >> 2;          // c/a-frag row within m16
    const int cq = (lane & 3) * 2;     // c/a-frag col-pair base within 8

    // ---- hoist layer-2 weights into registers (128 regs) ------------------
    uint32_t wx2r[4][4][4], wh2r[4][4][4];
#pragma unroll
    for (int kt = 0; kt < 4; kt++)
#pragma unroll
        for (int np = 0; np < 4; np++) {
            ldsm4(wx2r[kt][np], wx2B_lane + np * 16 * HSTRB + kt * 32);
            ldsm4(wh2r[kt][np], wh2B_lane + np * 16 * HSTRB + kt * 32);
        }
    __syncthreads();   // weights now in regs; staging area becomes free

    // ---- warp-private E' staging -----------------------------------------
    // ldsm reads use the shared-window u32 address; STORES use the GENERIC
    // pointer (sm + offset) -- R4 crashed by dereferencing the u32 address.
    const uint32_t stgA_lane = smb + OFF_STG + wid * STG_PER_WARP
                             + aRow * STGSTR + aK16;                 // ldsm read
    const int ldg_row   = lane >> 3;        // 0..3 within 4-row group
    const int ldg_chunk = lane & 7;         // 16B chunk within 128B row
    unsigned char* stg_ptr = sm + OFF_STG + wid * STG_PER_WARP + ldg_chunk * 16;

    // ---- per-lane b2 (layer-2 acc init) ----------------------------------
    float b2x[8], b2y[8];
#pragma unroll
    for (int nt = 0; nt < 8; nt++) {
        b2x[nt] = __ldg(b2 + nt * 8 + cq);
        b2y[nt] = __ldg(b2 + nt * 8 + cq + 1);
    }

    // ---- register-resident state fragments -------------------------------
    uint32_t h1f[4][4], h2f[4][4];
#pragma unroll
    for (int kt = 0; kt < 4; kt++)
#pragma unroll
        for (int j = 0; j < 4; j++) { h1f[kt][j] = 0u; h2f[kt][j] = 0u; }

    // ---- prefetch machinery ----------------------------------------------
    const uint4* Et4 = (const uint4*)g_Etab;   // 8 x uint4 per row
    uint4 pv[4];
    int tokreg = 0;

    auto prefetch_load = [&](int t) {
        int r = 0;
        if (lane < 16) r = __ldg(tokens + (size_t)(growbase + lane) * T_SEQ + t);
        tokreg = r;
#pragma unroll
        for (int i = 0; i < 4; i++) {
            int row = 4 * i + ldg_row;
            int tok = __shfl_sync(0xffffffffu, tokreg, row);
            pv[i] = __ldg(Et4 + (size_t)tok * 8 + ldg_chunk);
        }
    };
    auto prefetch_store = [&]() {
#pragma unroll
        for (int i = 0; i < 4; i++) {
            int row = 4 * i + ldg_row;
            *(uint4*)(stg_ptr + row * STGSTR) = pv[i];
        }
    };

    prefetch_load(0);
    prefetch_store();
    __syncwarp();

    // ---- T loop (state in regs; staging is the only steady SMEM traffic) --
    for (int t = 0; t < T_SEQ; ++t) {
        // acc init = xp from staged E' (ldsm4 per 16-col chunk -> C layout)
        float acc[8][4];
#pragma unroll
        for (int kc = 0; kc < 4; kc++) {
            uint32_t e[4]; ldsm4(e, stgA_lane + kc * 32);
            // e[0]=row cr k-lo, e[1]=row cr+8 k-lo, e[2]=row cr k-hi, e[3]=row cr+8 k-hi
            acc[2 * kc][0]     = bf16_lo(e[0]); acc[2 * kc][1]     = bf16_hi(e[0]);
            acc[2 * kc][2]     = bf16_lo(e[1]); acc[2 * kc][3]     = bf16_hi(e[1]);
            acc[2 * kc + 1][0] = bf16_lo(e[2]); acc[2 * kc + 1][1] = bf16_hi(e[2]);
            acc[2 * kc + 1][2] = bf16_lo(e[3]); acc[2 * kc + 1][3] = bf16_hi(e[3]);
        }
        __syncwarp();                       // all lanes done reading staging
        if (t + 1 < T_SEQ) prefetch_load(t + 1);   // LDGs overlap MMAs

        // ---- layer 1: acc += h1 @ Wh1 (B from SMEM) ----
#pragma unroll
        for (int kt = 0; kt < 4; kt++) {
#pragma unroll
            for (int np = 0; np < 4; np++) {
                uint32_t b[4]; ldsm4(b, wh1B_lane + np * 16 * HSTRB + kt * 32);
                mma16816(acc[2 * np],     h1f[kt], b[0], b[1]);
                mma16816(acc[2 * np + 1], h1f[kt], b[2], b[3]);
            }
        }

        // ---- epilogue 1: h1 = tanh(acc) -> register A-fragments ----
        // a-frag: [0]=row cr k-lo, [1]=row cr+8 k-lo, [2]=row cr k-hi, [3]=row cr+8 k-hi
#pragma unroll
        for (int kt = 0; kt < 4; kt++) {
            h1f[kt][0] = pack_bf16x2(tanh_fast(acc[2 * kt][0]),     tanh_fast(acc[2 * kt][1]));
            h1f[kt][1] = pack_bf16x2(tanh_fast(acc[2 * kt][2]),     tanh_fast(acc[2 * kt][3]));
            h1f[kt][2] = pack_bf16x2(tanh_fast(acc[2 * kt + 1][0]), tanh_fast(acc[2 * kt + 1][1]));
            h1f[kt][3] = pack_bf16x2(tanh_fast(acc[2 * kt + 1][2]), tanh_fast(acc[2 * kt + 1][3]));
        }

        if (t + 1 < T_SEQ) prefetch_store();   // STS mid-step (LDG data ready)

        // ---- layer 2: acc = b2 + h1 @ Wx2 + h2 @ Wh2 (B in regs) ----
#pragma unroll
        for (int nt = 0; nt < 8; nt++) {
            acc[nt][0] = b2x[nt]; acc[nt][1] = b2y[nt];
            acc[nt][2] = b2x[nt]; acc[nt][3] = b2y[nt];
        }
#pragma unroll
        for (int kt = 0; kt < 4; kt++) {
#pragma unroll
            for (int np = 0; np < 4; np++) {
                mma16816(acc[2 * np],     h1f[kt], wx2r[kt][np][0], wx2r[kt][np][1]);
                mma16816(acc[2 * np + 1], h1f[kt], wx2r[kt][np][2], wx2r[kt][np][3]);
            }
        }
#pragma unroll
        for (int kt = 0; kt < 4; kt++) {
#pragma unroll
            for (int np = 0; np < 4; np++) {
                mma16816(acc[2 * np],     h2f[kt], wh2r[kt][np][0], wh2r[kt][np][1]);
                mma16816(acc[2 * np + 1], h2f[kt], wh2r[kt][np][2], wh2r[kt][np][3]);
            }
        }

        // ---- epilogue 2: h2 = tanh(acc) -> register A-fragments ----
#pragma unroll
        for (int kt = 0; kt < 4; kt++) {
            h2f[kt][0] = pack_bf16x2(tanh_fast(acc[2 * kt][0]),     tanh_fast(acc[2 * kt][1]));
            h2f[kt][1] = pack_bf16x2(tanh_fast(acc[2 * kt][2]),     tanh_fast(acc[2 * kt][3]));
            h2f[kt][2] = pack_bf16x2(tanh_fast(acc[2 * kt + 1][0]), tanh_fast(acc[2 * kt + 1][1]));
            h2f[kt][3] = pack_bf16x2(tanh_fast(acc[2 * kt + 1][2]), tanh_fast(acc[2 * kt + 1][3]));
        }
        __syncwarp();    // staging stores visible for next iteration's ldsm
    }

    // ---- final dense + sigmoid from h2 register fragments ----------------
    // row cr: fragments [0] (cols 16kt+cq) and [2] (cols 16kt+8+cq)
    // row cr+8: fragments [1] and [3]
    {
        float la = 0.0f, lb = 0.0f;
#pragma unroll
        for (int kt = 0; kt < 4; kt++) {
            int c0 = 16 * kt + cq;
            float w0 = __ldg(Wd + c0),     float_w1 = __ldg(Wd + c0 + 1);
            float w8 = __ldg(Wd + c0 + 8), w9 = __ldg(Wd + c0 + 9);
            la = fmaf(bf16_lo(h2f[kt][0]), w0, la);
            la = fmaf(bf16_hi(h2f[kt][0]), float_w1, la);
            la = fmaf(bf16_lo(h2f[kt][2]), w8, la);
            la = fmaf(bf16_hi(h2f[kt][2]), w9, la);
            lb = fmaf(bf16_lo(h2f[kt][1]), w0, lb);
            lb = fmaf(bf16_hi(h2f[kt][1]), float_w1, lb);
            lb = fmaf(bf16_lo(h2f[kt][3]), w8, lb);
            lb = fmaf(bf16_hi(h2f[kt][3]), w9, lb);
        }
        la += __shfl_xor_sync(0xffffffffu, la, 1);
        la += __shfl_xor_sync(0xffffffffu, la, 2);
        lb += __shfl_xor_sync(0xffffffffu, lb, 1);
        lb += __shfl_xor_sync(0xffffffffu, lb, 2);
        if ((lane & 3) == 0) {
            float bdv = __ldg(bd);
            out[growbase + cr]     = 1.0f / (1.0f + __expf(-(la + bdv)));
            out[growbase + cr + 8] = 1.0f / (1.0f + __expf(-(lb + bdv)));
        }
    }
}

// ---------------------------------------------------------------------------
extern "C" void kernel_launch(void* const* d_in, const int* in_sizes, int n_in,
                              void* d_out, int out_size) {
    (void)in_sizes; (void)n_in; (void)out_size;
    cudaFuncSetAttribute(rnn_loop_kernel,
                         cudaFuncAttributeMaxDynamicSharedMemorySize, SMEM_TOTAL);

    xproj_kernel<<<(VOCAB + 3) / 4, dim3(64, 4)>>>(
        (const float*)d_in[1],   // emb
        (const float*)d_in[2],   // Wx1
        (const float*)d_in[4]);  // b1

    rnn_loop_kernel<<<B_TOT / M_TILE, NTHR, SMEM_TOTAL>>>(
        (const int*)d_in[0],     // tokens
        (const float*)d_in[3],   // Wh1
        (const float*)d_in[5],   // Wx2
        (const float*)d_in[6],   // Wh2
        (const float*)d_in[7],   // b2
        (const float*)d_in[8],   // Wd
        (const float*)d_in[9],   // bd
        (float*)d_out);
}